// round 5
// baseline (speedup 1.0000x reference)
#include <cuda_runtime.h>
#include <cstdint>
#include <cstddef>

#define NB  2
#define NH  12
#define HD  64
#define SEQ 2048
#define EMB 768
#define NCOL 2304  // 3*NH*HD

// Scratch. Q and K stored TRANSPOSED (b,h,d,n); V natural (b,h,n,d).
__device__ float g_Q[NB * NH * HD * SEQ];
__device__ float g_K[NB * NH * HD * SEQ];
__device__ float g_V[NB * NH * SEQ * HD];

typedef unsigned long long ull;

static __device__ __forceinline__ ull pack2(float lo, float hi) {
    ull r; asm("mov.b64 %0, {%1, %2};" : "=l"(r) : "f"(lo), "f"(hi)); return r;
}
static __device__ __forceinline__ void unpack2(float& lo, float& hi, ull v) {
    asm("mov.b64 {%0, %1}, %2;" : "=f"(lo), "=f"(hi) : "l"(v));
}
static __device__ __forceinline__ void fma2(ull& d, ull a, ull b) {
    asm("fma.rn.f32x2 %0, %1, %2, %0;" : "+l"(d) : "l"(a), "l"(b));
}

// ============================================================================
// Kernel 1: fused QKV GEMM + bias + scatter (Q,K transposed; V natural).
// ============================================================================
__global__ __launch_bounds__(256, 2)
void qkv_gemm_kernel(const float* __restrict__ z, const float* __restrict__ W,
                     const float* __restrict__ bias)
{
    __shared__ float As[16][132];
    __shared__ float Bs[16][128];

    const int tid = threadIdx.x;
    const int tx = tid & 15;
    const int ty = tid >> 4;
    const int m0 = blockIdx.y * 128;
    const int n0 = blockIdx.x * 128;

    ull acc[8][4];
#pragma unroll
    for (int i = 0; i < 8; i++)
#pragma unroll
        for (int j = 0; j < 4; j++) acc[i][j] = 0ull;

    float4 aL[2], bL[2];
#pragma unroll
    for (int i = 0; i < 2; i++) {
        int f = tid * 2 + i;
        aL[i] = *(const float4*)&z[(size_t)(m0 + (f >> 2)) * EMB + ((f & 3) << 2)];
        int e = tid + (i << 8);
        bL[i] = *(const float4*)&W[(size_t)(e >> 5) * NCOL + n0 + ((e & 31) << 2)];
    }

    for (int kt = 0; kt < 48; kt++) {
#pragma unroll
        for (int i = 0; i < 2; i++) {
            int f = tid * 2 + i;
            int row = f >> 2, kb = (f & 3) << 2;
            As[kb + 0][row] = aL[i].x; As[kb + 1][row] = aL[i].y;
            As[kb + 2][row] = aL[i].z; As[kb + 3][row] = aL[i].w;
            int e = tid + (i << 8);
            *(float4*)&Bs[e >> 5][(e & 31) << 2] = bL[i];
        }
        __syncthreads();

        if (kt < 47) {
            int kbase = (kt + 1) * 16;
#pragma unroll
            for (int i = 0; i < 2; i++) {
                int f = tid * 2 + i;
                aL[i] = *(const float4*)&z[(size_t)(m0 + (f >> 2)) * EMB + kbase + ((f & 3) << 2)];
                int e = tid + (i << 8);
                bL[i] = *(const float4*)&W[(size_t)(kbase + (e >> 5)) * NCOL + n0 + ((e & 31) << 2)];
            }
        }

#pragma unroll
        for (int kk = 0; kk < 16; kk++) {
            float4 a0 = *(const float4*)&As[kk][ty << 3];
            float4 a1 = *(const float4*)&As[kk][(ty << 3) + 4];
            ulonglong2 b0 = *(const ulonglong2*)&Bs[kk][tx << 3];
            ulonglong2 b1 = *(const ulonglong2*)&Bs[kk][(tx << 3) + 4];
            float av[8] = {a0.x, a0.y, a0.z, a0.w, a1.x, a1.y, a1.z, a1.w};
#pragma unroll
            for (int i = 0; i < 8; i++) {
                ull ad = pack2(av[i], av[i]);
                fma2(acc[i][0], ad, b0.x);
                fma2(acc[i][1], ad, b0.y);
                fma2(acc[i][2], ad, b1.x);
                fma2(acc[i][3], ad, b1.y);
            }
        }
        __syncthreads();
    }

    const int mrow = m0 + (ty << 3);
#pragma unroll
    for (int i = 0; i < 8; i++) {
        int row = mrow + i;
        int bb = row >> 11;
        int nn = row & 2047;
#pragma unroll
        for (int j = 0; j < 4; j++) {
            float lo, hi;
            unpack2(lo, hi, acc[i][j]);
            int c0 = n0 + (tx << 3) + j * 2;
#pragma unroll
            for (int u = 0; u < 2; u++) {
                int c = c0 + u;
                float v = (u == 0 ? lo : hi) + bias[c];
                int h = c / 192;
                int rem = c - h * 192;
                int d = rem / 3;
                int s = rem - d * 3;
                size_t bhf = (size_t)(bb * NH + h);
                if (s == 0)      g_K[(bhf * HD + d) * SEQ + nn] = v;
                else if (s == 1) g_V[(bhf * SEQ + nn) * HD + d] = v;
                else             g_Q[(bhf * HD + d) * SEQ + nn] = v;
            }
        }
    }
}

// ============================================================================
// Kernel 2: flash-style attention, fp32 f32x2, no-max softmax (logits bounded;
// shift cancels in O/l). Reference bug preserved: 0.125 applied post-softmax.
//
// 256 threads, BM=64 queries, BN=128 keys/tile, 16 tiles, 2 CTAs/SM.
// S phase:  qg = tid>>5 (8 x 8q, warp-uniform), kg = tid&31 (32 x 4k).
// PV phase: kh = tid>>7 (k half), qg2 = (tid>>3)&15 (4q), dg2 = tid&7 (8d);
//           partial O reduced across halves via smem at the end.
// Smem (floats): Qs[64][64] + Ks[64][128] + Vs[128][64] + Ps[64][128] = 112KB.
// ============================================================================
__global__ __launch_bounds__(256, 2)
void attn_kernel(float* __restrict__ out)
{
    extern __shared__ float sm[];
    float* Qs = sm;                         // [d][q]  64x64
    float* Ks = sm + 64 * 64;               // [d][k]  64x128 (reused as O-partial)
    float* Vs = sm + 64 * 64 + 64 * 128;    // [k][d]  128x64
    float* Ps = Vs + 128 * 64;              // [q][k]  64x128

    const int tid = threadIdx.x;
    const int lane = tid & 31;
    const int qg  = tid >> 5;           // S: q rows [qg*8, qg*8+8)
    const int kg  = lane;               // S: k cols [kg*4, kg*4+4)
    const int kh  = tid >> 7;           // PV: k half
    const int qg2 = (tid >> 3) & 15;    // PV: q rows [qg2*4, +4)
    const int dg2 = tid & 7;            // PV: d cols [dg2*8, +8)
    const int q0 = blockIdx.x << 6;
    const int bh = blockIdx.y;

    const float* QT = g_Q + (size_t)bh * HD * SEQ;
    const float* KT = g_K + (size_t)bh * HD * SEQ;
    const float* Vg = g_V + (size_t)bh * SEQ * HD;

    // Q tile: Qs[d][q], row-contiguous copies.
    {
        int d = tid >> 4;
        int c = (tid & 15) << 2;
#pragma unroll
        for (int i = 0; i < 4; i++)
            *(float4*)&Qs[(d + i * 16) * 64 + c] =
                *(const float4*)&QT[(size_t)(d + i * 16) * SEQ + q0 + c];
    }

    ull o2[4][4];
#pragma unroll
    for (int qi = 0; qi < 4; qi++)
#pragma unroll
        for (int j = 0; j < 4; j++) o2[qi][j] = 0ull;
    float lsum[8] = {0.f, 0.f, 0.f, 0.f, 0.f, 0.f, 0.f, 0.f};

    for (int kt = 0; kt < 16; kt++) {
        __syncthreads();   // prior PV done with Vs/Ps; Q store done (tile 0)
        const int k0 = kt << 7;

        // K tile: Ks[d][k] 64x128
        {
            int d = tid >> 5;
            int c = lane << 2;
#pragma unroll
            for (int i = 0; i < 8; i++)
                *(float4*)&Ks[(d + i * 8) * 128 + c] =
                    *(const float4*)&KT[(size_t)(d + i * 8) * SEQ + k0 + c];
        }
        // V tile: Vs[k][d] 128x64
        {
            int r = tid >> 4;
            int c = (tid & 15) << 2;
#pragma unroll
            for (int i = 0; i < 8; i++)
                *(float4*)&Vs[(r + i * 16) * 64 + c] =
                    *(const float4*)&Vg[(size_t)(k0 + r + i * 16) * HD + c];
        }
        __syncthreads();

        // S = Q^T K : 8q x 4k per thread.
        ull sacc[4][4];   // [k j][q pair]
#pragma unroll
        for (int j = 0; j < 4; j++)
#pragma unroll
            for (int p = 0; p < 4; p++) sacc[j][p] = 0ull;

        const float* qb = Qs + (qg << 3);
        const float* kb = Ks + (kg << 2);
#pragma unroll 4
        for (int d = 0; d < 64; d++) {
            ulonglong2 qA = *(const ulonglong2*)(qb + d * 64);
            ulonglong2 qB = *(const ulonglong2*)(qb + d * 64 + 4);
            float4 kA = *(const float4*)(kb + d * 128);
            ull qp[4] = {qA.x, qA.y, qB.x, qB.y};
            float kf[4] = {kA.x, kA.y, kA.z, kA.w};
#pragma unroll
            for (int j = 0; j < 4; j++) {
                ull kd = pack2(kf[j], kf[j]);
#pragma unroll
                for (int p = 0; p < 4; p++) fma2(sacc[j][p], qp[p], kd);
            }
        }

        // exp (no max shift), accumulate l, stage P q-major.
#pragma unroll
        for (int p = 0; p < 4; p++) {
            float r0[4], r1[4];
#pragma unroll
            for (int j = 0; j < 4; j++) {
                float s0, s1;
                unpack2(s0, s1, sacc[j][p]);
                r0[j] = __expf(s0);
                r1[j] = __expf(s1);
                lsum[2 * p]     += r0[j];
                lsum[2 * p + 1] += r1[j];
            }
            float* row0 = Ps + ((qg << 3) + 2 * p) * 128 + (kg << 2);
            *(float4*)row0         = make_float4(r0[0], r0[1], r0[2], r0[3]);
            *(float4*)(row0 + 128) = make_float4(r1[0], r1[1], r1[2], r1[3]);
        }
        __syncthreads();

        // O += P V : 4q x 8d per thread over this thread's 64-k half.
        const float* pb = Ps + (qg2 << 2) * 128 + (kh << 6);
        const float* vb = Vs + (kh << 6) * 64 + (dg2 << 3);
#pragma unroll 2
        for (int k4 = 0; k4 < 64; k4 += 4) {
            float4 p4[4];
#pragma unroll
            for (int qi = 0; qi < 4; qi++)
                p4[qi] = *(const float4*)(pb + qi * 128 + k4);
#pragma unroll
            for (int kk = 0; kk < 4; kk++) {
                ulonglong2 va = *(const ulonglong2*)(vb + (k4 + kk) * 64);
                ulonglong2 vc = *(const ulonglong2*)(vb + (k4 + kk) * 64 + 4);
#pragma unroll
                for (int qi = 0; qi < 4; qi++) {
                    const float* pf = (const float*)&p4[qi];
                    ull pd = pack2(pf[kk], pf[kk]);
                    fma2(o2[qi][0], pd, va.x);
                    fma2(o2[qi][1], pd, va.y);
                    fma2(o2[qi][2], pd, vc.x);
                    fma2(o2[qi][3], pd, vc.y);
                }
            }
        }
    }

    // l: reduce across all 32 lanes (kg spans the full 128 k per warp).
#pragma unroll
    for (int qi = 0; qi < 8; qi++) {
#pragma unroll
        for (int off = 16; off > 0; off >>= 1)
            lsum[qi] += __shfl_xor_sync(0xffffffffu, lsum[qi], off);
    }
    if (lane == 0) {
#pragma unroll
        for (int qi = 0; qi < 8; qi++) Qs[(qg << 3) + qi] = lsum[qi];
    }

    // half-1 stages its partial O in smem (reuse Ks region, pitch 68).
    if (kh == 1) {
#pragma unroll
        for (int qi = 0; qi < 4; qi++) {
            float* dst = Ks + ((qg2 << 2) + qi) * 68 + (dg2 << 3);
            *(ull*)dst       = o2[qi][0];
            *(ull*)(dst + 2) = o2[qi][1];
            *(ull*)(dst + 4) = o2[qi][2];
            *(ull*)(dst + 6) = o2[qi][3];
        }
    }
    __syncthreads();

    if (kh == 0) {
        const int b = bh / NH;
        const int h = bh - b * NH;
#pragma unroll
        for (int qi = 0; qi < 4; qi++) {
            int row = (qg2 << 2) + qi;
            float inv = 0.125f / Qs[row];
            const float* src = Ks + row * 68 + (dg2 << 3);
            float v[8], w[8];
            unpack2(v[0], v[1], o2[qi][0]);
            unpack2(v[2], v[3], o2[qi][1]);
            unpack2(v[4], v[5], o2[qi][2]);
            unpack2(v[6], v[7], o2[qi][3]);
#pragma unroll
            for (int u = 0; u < 8; u++) w[u] = (v[u] + src[u]) * inv;
            int n = q0 + row;
            float* dst = out + ((size_t)(b * SEQ + n)) * EMB + h * HD + (dg2 << 3);
            *(float4*)dst       = make_float4(w[0], w[1], w[2], w[3]);
            *(float4*)(dst + 4) = make_float4(w[4], w[5], w[6], w[7]);
        }
    }
}

// ============================================================================
extern "C" void kernel_launch(void* const* d_in, const int* in_sizes, int n_in,
                              void* d_out, int out_size)
{
    const float* z = nullptr;
    const float* W = nullptr;
    const float* bias = nullptr;
    for (int i = 0; i < n_in; i++) {
        if (in_sizes[i] == NB * SEQ * EMB)      z = (const float*)d_in[i];
        else if (in_sizes[i] == EMB * NCOL)     W = (const float*)d_in[i];
        else if (in_sizes[i] == NCOL)           bias = (const float*)d_in[i];
    }
    float* out = (float*)d_out;

    dim3 g1(NCOL / 128, (NB * SEQ) / 128);   // (18, 32)
    qkv_gemm_kernel<<<g1, 256>>>(z, W, bias);

    const int smem_bytes = (64 * 64 + 64 * 128 + 128 * 64 + 64 * 128)
                           * (int)sizeof(float);  // 114688
    cudaFuncSetAttribute(attn_kernel, cudaFuncAttributeMaxDynamicSharedMemorySize,
                         smem_bytes);
    dim3 g2(SEQ / 64, NB * NH);              // (32, 24)
    attn_kernel<<<g2, 256, smem_bytes>>>(out);
}